// round 7
// baseline (speedup 1.0000x reference)
#include <cuda_runtime.h>
#include <math.h>

#define NS        100
#define NPIX      (NS * NS)
#define PARTS     8
#define MAXPARTS  16
#define BLOCK     256
#define NW        (BLOCK / 32)
#define U         4
#define INF_F     1000000000.0f
#define MU_F      1e-8f
#define SAFE_THR  0.05f

__device__ __forceinline__ float fsqrt_approx(float x) {
    float r; asm("sqrt.approx.f32 %0, %1;" : "=f"(r) : "f"(x)); return r;
}
__device__ __forceinline__ float frcp_approx(float x) {
    float r; asm("rcp.approx.f32 %0, %1;" : "=f"(r) : "f"(x)); return r;
}

__global__ __launch_bounds__(BLOCK)
void pc_kernel(const float* __restrict__ seg_maps,      // (B,100,100)
               const float* __restrict__ seg_map_paras, // (B,6)
               const float* __restrict__ trajectories,  // (B,8,2)
               const float* __restrict__ current_pos,   // (B,1,2)
               float* __restrict__ out)                 // (B,16,3)
{
    const int b    = blockIdx.x;
    const int tid  = threadIdx.x;
    const int lane = tid & 31;
    const int wid  = tid >> 5;

    __shared__ float sp[8];      // invW0, invW1, offI, offJ, r2, swap, ml
    __shared__ int   sbb[4];     // il, Hd, qlo, nq
    __shared__ int   smin[PARTS];

    if (tid < PARTS) smin[tid] = __float_as_int(INF_F);
    if (tid == 0) {
        const float* pr = seg_map_paras + b * 6;
        float W0 = pr[0], W1 = pr[1], b0 = pr[2], b1 = pr[3], order0 = pr[4];
        bool swap = (order0 == 1.0f);

        const float* tr = trajectories + b * 16;
        float mvx = tr[14] - tr[0];
        float mvy = tr[15] - tr[1];
        float ml  = sqrtf(mvx * mvx + mvy * mvy);
        float r   = 2.0f * ml;

        float cx = current_pos[b * 2 + 0];
        float cy = current_pos[b * 2 + 1];

        float invW0 = 1.0f / W0;
        float invW1 = 1.0f / W1;
        float offI = -b0 * invW0 - (swap ? cy : cx);
        float offJ = -b1 * invW1 - (swap ? cx : cy);

        sp[0] = invW0; sp[1] = invW1; sp[2] = offI; sp[3] = offJ;
        sp[4] = r * r; sp[5] = swap ? 1.0f : 0.0f; sp[6] = ml;

        // conservative pixel-space bbox of the valid disk (+/-1 px margin).
        // pixels outside [jl,jh]/[il,ih] are guaranteed dd > r2, so widening
        // the scanned range never changes the result.
        int il = (int)floorf((-r - offI) * W0) - 1;
        int ih = (int)ceilf (( r - offI) * W0) + 1;
        int jl = (int)floorf((-r - offJ) * W1) - 1;
        int jh = (int)ceilf (( r - offJ) * W1) + 1;
        il = max(il, 0);  ih = min(ih, NS - 1);
        jl = max(jl, 0);  jh = min(jh, NS - 1);
        int qlo = jl >> 2;                 // first quad of row segment
        int nq  = (jh >> 2) - qlo + 1;     // quad count (<= 25, fits one warp)
        sbb[0] = il;
        sbb[1] = ih - il + 1;              // Hd (<=0 if empty)
        sbb[2] = qlo;
        sbb[3] = (jh >= jl) ? nq : 0;
    }
    __syncthreads();

    const float invW0 = sp[0], invW1 = sp[1], offI = sp[2], offJ = sp[3];
    const float r2 = sp[4];
    const bool  swp = (sp[5] != 0.0f);
    const int il = sbb[0], Hd = sbb[1], qlo = sbb[2], nq = sbb[3];

    float lmin[PARTS];
#pragma unroll
    for (int p = 0; p < PARTS; ++p) lmin[p] = INF_F;

    const float* mp = seg_maps + (size_t)b * NPIX;

    // lane <-> one float4 (4 columns); a single warp spans the whole j-extent.
    const bool qok = (lane < nq);
    const int  q   = qlo + lane;
    float dJ[4], dJ2[4];
#pragma unroll
    for (int c = 0; c < 4; ++c) {
        dJ[c]  = fmaf((float)(4 * q + c), invW1, offJ);
        dJ2[c] = dJ[c] * dJ[c];
    }

    for (int rb = wid * U; rb < Hd; rb += NW * U) {
        float4 mv[U];
        float  dI[U];
        bool   act[U];
#pragma unroll
        for (int k = 0; k < U; ++k) {
            int r = rb + k;
            act[k] = qok && (r < Hd);
            int i  = il + r;
            dI[k]  = fmaf((float)i, invW0, offI);
            mv[k]  = act[k] ? __ldg((const float4*)(mp + i * NS) + q)
                            : make_float4(0.f, 0.f, 0.f, 0.f);
        }
#pragma unroll
        for (int k = 0; k < U; ++k) {
            float dirI  = dI[k];
            float dirI2 = dirI * dirI;
            float mc[4] = { mv[k].x, mv[k].y, mv[k].z, mv[k].w };
#pragma unroll
            for (int c = 0; c < 4; ++c) {
                float m  = mc[c];
                float dd = fmaf(dirI, dirI, dJ2[c]);   // == dirI2 + dJ2
                (void)dirI2;
                if (act[k] && m > SAFE_THR && dd <= r2) {
                    float dist = fsqrt_approx(dd);
                    float eq   = (dist + MU_F) * frcp_approx(m + MU_F);
                    float sv = swp ? dJ[c] : dirI;   // angle = atan2(sv, cv)
                    float cv = swp ? dirI  : dJ[c];
                    int bin;
                    if (sv >= 0.0f) {
                        if (cv >= 0.0f) bin = (sv <= cv)  ? 0 : 1;
                        else            bin = (sv >= -cv) ? 2 : 3;
                    } else {
                        if (cv <= 0.0f) bin = (-sv <= -cv) ? 4 : 5;
                        else            bin = (-sv >= cv)  ? 6 : 7;
                    }
#pragma unroll
                    for (int p = 0; p < PARTS; ++p)
                        lmin[p] = (bin == p) ? fminf(lmin[p], eq) : lmin[p];
                }
            }
        }
    }

    // warp min-reduce per bin, then one smem atomic per warp per bin
#pragma unroll
    for (int p = 0; p < PARTS; ++p) {
        float v = lmin[p];
#pragma unroll
        for (int o = 16; o > 0; o >>= 1)
            v = fminf(v, __shfl_xor_sync(0xffffffffu, v, o));
        if (lane == 0)
            atomicMin(&smin[p], __float_as_int(v));  // values >= 0: int order == float order
    }
    __syncthreads();

    if (tid < MAXPARTS) {
        float fv = 0.0f, fd = 0.0f, fr = 0.0f;
        if (tid < PARTS) {
            float md = fminf(__int_as_float(smin[tid]), INF_F);
            if (md < INF_F) {
                fv = sp[6];   // ml
                fd = md;
                fr = (float)(6.283185307179586 * ((double)tid + 0.5) / 8.0);
            }
        }
        float* o = out + (size_t)b * (MAXPARTS * 3) + tid * 3;
        o[0] = fv; o[1] = fd; o[2] = fr;
    }
}

extern "C" void kernel_launch(void* const* d_in, const int* in_sizes, int n_in,
                              void* d_out, int out_size)
{
    const float* seg_maps      = (const float*)d_in[0];
    const float* seg_map_paras = (const float*)d_in[1];
    const float* trajectories  = (const float*)d_in[2];
    const float* current_pos   = (const float*)d_in[3];
    float* out = (float*)d_out;

    int B = in_sizes[0] / NPIX;   // 1024
    pc_kernel<<<B, BLOCK>>>(seg_maps, seg_map_paras, trajectories,
                            current_pos, out);
}

// round 8
// speedup vs baseline: 1.0847x; 1.0847x over previous
#include <cuda_runtime.h>
#include <math.h>

#define NS        100
#define NPIX      (NS * NS)
#define PARTS     8
#define MAXPARTS  16
#define BLOCK     256
#define NW        (BLOCK / 32)
#define U         4
#define INF_F     1000000000.0f
#define MU_F      1e-8f
#define SAFE_THR  0.05f

__device__ __forceinline__ float fsqrt_approx(float x) {
    float r; asm("sqrt.approx.f32 %0, %1;" : "=f"(r) : "f"(x)); return r;
}
__device__ __forceinline__ float frcp_approx(float x) {
    float r; asm("rcp.approx.f32 %0, %1;" : "=f"(r) : "f"(x)); return r;
}

__global__ __launch_bounds__(BLOCK)
void pc_kernel(const float* __restrict__ seg_maps,      // (B,100,100)
               const float* __restrict__ seg_map_paras, // (B,6)
               const float* __restrict__ trajectories,  // (B,8,2)
               const float* __restrict__ current_pos,   // (B,1,2)
               float* __restrict__ out)                 // (B,16,3)
{
    const int b    = blockIdx.x;
    const int tid  = threadIdx.x;
    const int lane = tid & 31;
    const int wid  = tid >> 5;

    __shared__ float sp[8];      // invW0, invW1, offI, offJ, r2, swap, ml
    __shared__ int   sbb[5];     // il, Hd, qlo, nq, lg
    __shared__ int   smin[PARTS];

    if (tid < PARTS) smin[tid] = __float_as_int(INF_F);
    if (tid == 0) {
        const float* pr = seg_map_paras + b * 6;
        float W0 = pr[0], W1 = pr[1], b0 = pr[2], b1 = pr[3], order0 = pr[4];
        bool swap = (order0 == 1.0f);

        const float* tr = trajectories + b * 16;
        float mvx = tr[14] - tr[0];
        float mvy = tr[15] - tr[1];
        float ml  = sqrtf(mvx * mvx + mvy * mvy);
        float r   = 2.0f * ml;

        float cx = current_pos[b * 2 + 0];
        float cy = current_pos[b * 2 + 1];

        float invW0 = 1.0f / W0;
        float invW1 = 1.0f / W1;
        float offI = -b0 * invW0 - (swap ? cy : cx);
        float offJ = -b1 * invW1 - (swap ? cx : cy);

        sp[0] = invW0; sp[1] = invW1; sp[2] = offI; sp[3] = offJ;
        sp[4] = r * r; sp[5] = swap ? 1.0f : 0.0f; sp[6] = ml;

        // conservative pixel-space bbox of the valid disk (+/-1 px margin).
        // scanning extra pixels never changes the result (exact dd<=r2 test).
        int il = (int)floorf((-r - offI) * W0) - 1;
        int ih = (int)ceilf (( r - offI) * W0) + 1;
        int jl = (int)floorf((-r - offJ) * W1) - 1;
        int jh = (int)ceilf (( r - offJ) * W1) + 1;
        il = max(il, 0);  ih = min(ih, NS - 1);
        jl = max(jl, 0);  jh = min(jh, NS - 1);
        int qlo = jl >> 2;
        int nq  = (jh >= jl) ? ((jh >> 2) - qlo + 1) : 0;   // <= 25
        int lg = 0;
        while ((1 << lg) < nq) ++lg;                        // qspan = 2^lg >= nq
        sbb[0] = il;
        sbb[1] = ih - il + 1;   // Hd
        sbb[2] = qlo;
        sbb[3] = nq;
        sbb[4] = lg;            // 0..5
    }
    __syncthreads();

    const float invW0 = sp[0], invW1 = sp[1], offI = sp[2], offJ = sp[3];
    const float r2 = sp[4];
    const bool  swp = (sp[5] != 0.0f);
    const int il = sbb[0], Hd = sbb[1], qlo = sbb[2], nq = sbb[3], lg = sbb[4];

    // adaptive 2-D lane mapping: lane -> (row_sub, quad)
    const int mask = (1 << lg) - 1;
    const int qsub = lane & mask;          // quad within span
    const int rsub = lane >> lg;           // row within warp round
    const int rpw  = 32 >> lg;             // rows per warp per k-step
    const bool qok = (qsub < nq);
    const int  q   = qlo + qsub;

    float dJ[4], dJ2[4];
#pragma unroll
    for (int c = 0; c < 4; ++c) {
        dJ[c]  = fmaf((float)(4 * q + c), invW1, offJ);
        dJ2[c] = dJ[c] * dJ[c];
    }

    float lmin[PARTS];
#pragma unroll
    for (int p = 0; p < PARTS; ++p) lmin[p] = INF_F;

    const float* mp = seg_maps + (size_t)b * NPIX;

    const int warp_rows = rpw * U;              // rows per warp per loop iter
    for (int rb = wid * warp_rows; rb < Hd; rb += NW * warp_rows) {
        float4 mv[U];
        float  dI[U];
        bool   act[U];
#pragma unroll
        for (int k = 0; k < U; ++k) {
            int r = rb + k * rpw + rsub;
            act[k] = qok && (r < Hd);
            int i  = il + r;
            dI[k]  = fmaf((float)i, invW0, offI);
            mv[k]  = act[k] ? __ldg((const float4*)(mp + i * NS) + q)
                            : make_float4(0.f, 0.f, 0.f, 0.f);
        }
#pragma unroll
        for (int k = 0; k < U; ++k) {
            float dirI = dI[k];
            float mc[4] = { mv[k].x, mv[k].y, mv[k].z, mv[k].w };
#pragma unroll
            for (int c = 0; c < 4; ++c) {
                float m  = mc[c];
                float dd = fmaf(dirI, dirI, dJ2[c]);
                if (act[k] && m > SAFE_THR && dd <= r2) {
                    float dist = fsqrt_approx(dd);
                    float eq   = (dist + MU_F) * frcp_approx(m + MU_F);
                    float sv = swp ? dJ[c] : dirI;   // angle = atan2(sv, cv)
                    float cv = swp ? dirI  : dJ[c];
                    int bin;
                    if (sv >= 0.0f) {
                        if (cv >= 0.0f) bin = (sv <= cv)  ? 0 : 1;
                        else            bin = (sv >= -cv) ? 2 : 3;
                    } else {
                        if (cv <= 0.0f) bin = (-sv <= -cv) ? 4 : 5;
                        else            bin = (-sv >= cv)  ? 6 : 7;
                    }
#pragma unroll
                    for (int p = 0; p < PARTS; ++p)
                        lmin[p] = (bin == p) ? fminf(lmin[p], eq) : lmin[p];
                }
            }
        }
    }

    // warp min-reduce per bin, then one smem atomic per warp per bin
#pragma unroll
    for (int p = 0; p < PARTS; ++p) {
        float v = lmin[p];
#pragma unroll
        for (int o = 16; o > 0; o >>= 1)
            v = fminf(v, __shfl_xor_sync(0xffffffffu, v, o));
        if (lane == 0)
            atomicMin(&smin[p], __float_as_int(v));  // values >= 0: int order == float order
    }
    __syncthreads();

    if (tid < MAXPARTS) {
        float fv = 0.0f, fd = 0.0f, fr = 0.0f;
        if (tid < PARTS) {
            float md = fminf(__int_as_float(smin[tid]), INF_F);
            if (md < INF_F) {
                fv = sp[6];   // ml
                fd = md;
                fr = (float)(6.283185307179586 * ((double)tid + 0.5) / 8.0);
            }
        }
        float* o = out + (size_t)b * (MAXPARTS * 3) + tid * 3;
        o[0] = fv; o[1] = fd; o[2] = fr;
    }
}

extern "C" void kernel_launch(void* const* d_in, const int* in_sizes, int n_in,
                              void* d_out, int out_size)
{
    const float* seg_maps      = (const float*)d_in[0];
    const float* seg_map_paras = (const float*)d_in[1];
    const float* trajectories  = (const float*)d_in[2];
    const float* current_pos   = (const float*)d_in[3];
    float* out = (float*)d_out;

    int B = in_sizes[0] / NPIX;   // 1024
    pc_kernel<<<B, BLOCK>>>(seg_maps, seg_map_paras, trajectories,
                            current_pos, out);
}

// round 9
// speedup vs baseline: 1.2549x; 1.1569x over previous
#include <cuda_runtime.h>
#include <math.h>

#define NS        100
#define NPIX      (NS * NS)
#define PARTS     8
#define MAXPARTS  16
#define BLOCK     256
#define U         8
#define INF_F     1000000000.0f
#define MU_F      1e-8f
#define SAFE_THR  0.05f

__device__ __forceinline__ float fsqrt_approx(float x) {
    float r; asm("sqrt.approx.f32 %0, %1;" : "=f"(r) : "f"(x)); return r;
}
__device__ __forceinline__ float frcp_approx(float x) {
    float r; asm("rcp.approx.f32 %0, %1;" : "=f"(r) : "f"(x)); return r;
}

__global__ __launch_bounds__(BLOCK)
void pc_kernel(const float* __restrict__ seg_maps,      // (B,100,100)
               const float* __restrict__ seg_map_paras, // (B,6)
               const float* __restrict__ trajectories,  // (B,8,2)
               const float* __restrict__ current_pos,   // (B,1,2)
               float* __restrict__ out)                 // (B,16,3)
{
    const int b    = blockIdx.x;
    const int tid  = threadIdx.x;
    const int lane = tid & 31;

    __shared__ float sp[8];       // invW0, invW1, offI', offJ', r2, swap, ml
    __shared__ int   sbi[5];      // tot, Wd, magic, baseoff, (pad)
    __shared__ int   smin[PARTS];

    if (tid < PARTS) smin[tid] = __float_as_int(INF_F);
    if (tid == 0) {
        const float* pr = seg_map_paras + b * 6;
        float W0 = pr[0], W1 = pr[1], b0 = pr[2], b1 = pr[3], order0 = pr[4];
        bool swap = (order0 == 1.0f);

        const float* tr = trajectories + b * 16;
        float mvx = tr[14] - tr[0];
        float mvy = tr[15] - tr[1];
        float ml  = sqrtf(mvx * mvx + mvy * mvy);
        float r   = 2.0f * ml;

        float cx = current_pos[b * 2 + 0];
        float cy = current_pos[b * 2 + 1];

        float invW0 = 1.0f / W0;
        float invW1 = 1.0f / W1;
        float offI = -b0 * invW0 - (swap ? cy : cx);
        float offJ = -b1 * invW1 - (swap ? cx : cy);

        // conservative pixel-space bbox of the valid disk (+/-1 px margin);
        // scanning extra pixels never changes the result (exact dd<=r2 test).
        int il = (int)floorf((-r - offI) * W0) - 1;
        int ih = (int)ceilf (( r - offI) * W0) + 1;
        int jl = (int)floorf((-r - offJ) * W1) - 1;
        int jh = (int)ceilf (( r - offJ) * W1) + 1;
        il = max(il, 0);  ih = min(ih, NS - 1);
        jl = max(jl, 0);  jh = min(jh, NS - 1);

        // force Wd >= 2 so the magic constant fits in 32 bits (harmless widening)
        if (jh == jl) { if (jh < NS - 1) ++jh; else --jl; }

        int Wd = jh - jl + 1;
        int Hd = ih - il + 1;
        int tot = (Wd > 0 && Hd > 0) ? Wd * Hd : 0;

        // exact division by Wd for idx < 2^21/(Wd-1):
        // qi = umulhi(idx, M) where M = ceil(2^21/Wd) << 11
        unsigned M = ((2097152u + (unsigned)Wd - 1u) / (unsigned)Wd) << 11;

        sp[0] = invW0; sp[1] = invW1;
        sp[2] = fmaf((float)il, invW0, offI);   // offI' (qi-relative)
        sp[3] = fmaf((float)jl, invW1, offJ);   // offJ' (qj-relative)
        sp[4] = r * r; sp[5] = swap ? 1.0f : 0.0f; sp[6] = ml;

        sbi[0] = tot;
        sbi[1] = Wd;
        sbi[2] = (int)M;
        sbi[3] = il * NS + jl;                  // base offset into map
    }
    __syncthreads();

    const float invW0 = sp[0], invW1 = sp[1], offIp = sp[2], offJp = sp[3];
    const float r2 = sp[4];
    const bool  swp = (sp[5] != 0.0f);
    const int tot = sbi[0], Wd = sbi[1];
    const unsigned M = (unsigned)sbi[2];
    const float* base = seg_maps + (size_t)b * NPIX + sbi[3];
    const int rowadj = NS - Wd;                 // addr = idx + qi*rowadj

    float lmin[PARTS];
#pragma unroll
    for (int p = 0; p < PARTS; ++p) lmin[p] = INF_F;

    for (int lo = 0; lo < tot; lo += BLOCK * U) {
        float mv[U];
        int   qv[U];
#pragma unroll
        for (int k = 0; k < U; ++k) {
            int idx = lo + k * BLOCK + tid;
            int cidx = (idx < tot) ? idx : 0;           // clamp (safe, in-bounds)
            int qi  = (int)__umulhi((unsigned)cidx, M); // exact cidx / Wd
            qv[k]   = (qi << 16) | (cidx - qi * Wd);    // pack qi,qj
            mv[k]   = (idx < tot) ? __ldg(base + cidx + qi * rowadj) : 0.0f;
        }
#pragma unroll
        for (int k = 0; k < U; ++k) {
            int idx = lo + k * BLOCK + tid;
            float m  = mv[k];
            int qi = qv[k] >> 16;
            int qj = qv[k] & 0xFFFF;
            float dirI = fmaf((float)qi, invW0, offIp);
            float dirJ = fmaf((float)qj, invW1, offJp);
            float dd   = fmaf(dirJ, dirJ, dirI * dirI);
            if (idx < tot && m > SAFE_THR && dd <= r2) {
                float dist = fsqrt_approx(dd);
                float eq   = (dist + MU_F) * frcp_approx(m + MU_F);
                float sv = swp ? dirJ : dirI;   // angle = atan2(sv, cv)
                float cv = swp ? dirI : dirJ;
                int bin;
                if (sv >= 0.0f) {
                    if (cv >= 0.0f) bin = (sv <= cv)  ? 0 : 1;
                    else            bin = (sv >= -cv) ? 2 : 3;
                } else {
                    if (cv <= 0.0f) bin = (-sv <= -cv) ? 4 : 5;
                    else            bin = (-sv >= cv)  ? 6 : 7;
                }
#pragma unroll
                for (int p = 0; p < PARTS; ++p)
                    lmin[p] = (bin == p) ? fminf(lmin[p], eq) : lmin[p];
            }
        }
    }

    // warp min-reduce per bin, then one smem atomic per warp per bin
#pragma unroll
    for (int p = 0; p < PARTS; ++p) {
        float v = lmin[p];
#pragma unroll
        for (int o = 16; o > 0; o >>= 1)
            v = fminf(v, __shfl_xor_sync(0xffffffffu, v, o));
        if (lane == 0)
            atomicMin(&smin[p], __float_as_int(v));  // values >= 0: int order == float order
    }
    __syncthreads();

    if (tid < MAXPARTS) {
        float fv = 0.0f, fd = 0.0f, fr = 0.0f;
        if (tid < PARTS) {
            float md = fminf(__int_as_float(smin[tid]), INF_F);
            if (md < INF_F) {
                fv = sp[6];   // ml
                fd = md;
                fr = (float)(6.283185307179586 * ((double)tid + 0.5) / 8.0);
            }
        }
        float* o = out + (size_t)b * (MAXPARTS * 3) + tid * 3;
        o[0] = fv; o[1] = fd; o[2] = fr;
    }
}

extern "C" void kernel_launch(void* const* d_in, const int* in_sizes, int n_in,
                              void* d_out, int out_size)
{
    const float* seg_maps      = (const float*)d_in[0];
    const float* seg_map_paras = (const float*)d_in[1];
    const float* trajectories  = (const float*)d_in[2];
    const float* current_pos   = (const float*)d_in[3];
    float* out = (float*)d_out;

    int B = in_sizes[0] / NPIX;   // 1024
    pc_kernel<<<B, BLOCK>>>(seg_maps, seg_map_paras, trajectories,
                            current_pos, out);
}

// round 10
// speedup vs baseline: 1.2800x; 1.0200x over previous
#include <cuda_runtime.h>
#include <math.h>

#define NS        100
#define NPIX      (NS * NS)
#define PARTS     8
#define MAXPARTS  16
#define BLOCK     256
#define U         8
#define INF_F     1000000000.0f
#define MU_F      1e-8f
#define SAFE_THR  0.05f

__device__ __forceinline__ float fsqrt_approx(float x) {
    float r; asm("sqrt.approx.f32 %0, %1;" : "=f"(r) : "f"(x)); return r;
}
__device__ __forceinline__ float frcp_approx(float x) {
    float r; asm("rcp.approx.f32 %0, %1;" : "=f"(r) : "f"(x)); return r;
}

__global__ __launch_bounds__(BLOCK, 5)
void pc_kernel(const float* __restrict__ seg_maps,      // (B,100,100)
               const float* __restrict__ seg_map_paras, // (B,6)
               const float* __restrict__ trajectories,  // (B,8,2)
               const float* __restrict__ current_pos,   // (B,1,2)
               float* __restrict__ out)                 // (B,16,3)
{
    const int b    = blockIdx.x;
    const int tid  = threadIdx.x;
    const int lane = tid & 31;

    __shared__ float sraw[12];    // parallel-loaded raw scalars
    __shared__ float sp[8];       // invW0, invW1, offI', offJ', r2, swap, ml
    __shared__ int   sbi[4];      // tot, Wd, magic, baseoff
    __shared__ int   smin[PARTS];

    // one parallel memory round instead of a serial tid0 chain
    if (tid < 6)       sraw[tid] = __ldg(seg_map_paras + b * 6 + tid);
    else if (tid < 8)  sraw[tid] = __ldg(trajectories + b * 16 + (tid - 6));        // tr[0], tr[1]
    else if (tid < 10) sraw[tid] = __ldg(trajectories + b * 16 + 14 + (tid - 8));   // tr[14], tr[15]
    else if (tid < 12) sraw[tid] = __ldg(current_pos + b * 2 + (tid - 10));         // cx, cy
    if (tid < PARTS)   smin[tid] = __float_as_int(INF_F);
    __syncthreads();

    if (tid == 0) {
        float W0 = sraw[0], W1 = sraw[1], b0 = sraw[2], b1 = sraw[3], order0 = sraw[4];
        bool swap = (order0 == 1.0f);

        float mvx = sraw[8] - sraw[6];
        float mvy = sraw[9] - sraw[7];
        float ml  = sqrtf(mvx * mvx + mvy * mvy);
        float r   = 2.0f * ml;

        float cx = sraw[10], cy = sraw[11];

        float invW0 = 1.0f / W0;
        float invW1 = 1.0f / W1;
        float offI = -b0 * invW0 - (swap ? cy : cx);
        float offJ = -b1 * invW1 - (swap ? cx : cy);

        // conservative pixel-space bbox of the valid disk (+/-1 px margin);
        // scanning extra pixels never changes the result (exact dd<=r2 test).
        int il = (int)floorf((-r - offI) * W0) - 1;
        int ih = (int)ceilf (( r - offI) * W0) + 1;
        int jl = (int)floorf((-r - offJ) * W1) - 1;
        int jh = (int)ceilf (( r - offJ) * W1) + 1;
        il = max(il, 0);  ih = min(ih, NS - 1);
        jl = max(jl, 0);  jh = min(jh, NS - 1);

        // force Wd >= 2 so the magic constant fits in 32 bits (harmless widening)
        if (jh == jl) { if (jh < NS - 1) ++jh; else --jl; }

        int Wd = jh - jl + 1;
        int Hd = ih - il + 1;
        int tot = (Wd > 0 && Hd > 0) ? Wd * Hd : 0;

        // exact division by Wd for idx <= 10000: qi = umulhi(idx, M)
        unsigned M = ((2097152u + (unsigned)Wd - 1u) / (unsigned)Wd) << 11;

        sp[0] = invW0; sp[1] = invW1;
        sp[2] = fmaf((float)il, invW0, offI);   // offI' (qi-relative)
        sp[3] = fmaf((float)jl, invW1, offJ);   // offJ' (qj-relative)
        sp[4] = r * r; sp[5] = swap ? 1.0f : 0.0f; sp[6] = ml;

        sbi[0] = tot;
        sbi[1] = Wd;
        sbi[2] = (int)M;
        sbi[3] = il * NS + jl;
    }
    __syncthreads();

    const float invW0 = sp[0], invW1 = sp[1], offIp = sp[2], offJp = sp[3];
    const float r2 = sp[4];
    const bool  swp = (sp[5] != 0.0f);
    const int tot = sbi[0], Wd = sbi[1];
    const unsigned M = (unsigned)sbi[2];
    const float* base = seg_maps + (size_t)b * NPIX + sbi[3];
    const int rowadj = NS - Wd;                 // addr = idx + qi*rowadj

    float lmin[PARTS];
#pragma unroll
    for (int p = 0; p < PARTS; ++p) lmin[p] = INF_F;

    for (int lo = 0; lo < tot; lo += BLOCK * U) {
        float mv[U];
#pragma unroll
        for (int k = 0; k < U; ++k) {
            int idx = lo + k * BLOCK + tid;
            int cidx = (idx < tot) ? idx : 0;           // clamped, in-bounds
            int qi  = (int)__umulhi((unsigned)cidx, M); // exact cidx / Wd
            mv[k]   = (idx < tot) ? __ldg(base + cidx + qi * rowadj) : 0.0f;
        }
#pragma unroll
        for (int k = 0; k < U; ++k) {
            int idx = lo + k * BLOCK + tid;
            int cidx = (idx < tot) ? idx : 0;
            int qi = (int)__umulhi((unsigned)cidx, M);
            int qj = cidx - qi * Wd;
            float m    = mv[k];
            float dirI = fmaf((float)qi, invW0, offIp);
            float dirJ = fmaf((float)qj, invW1, offJp);
            float dd   = fmaf(dirJ, dirJ, dirI * dirI);
            if (idx < tot && m > SAFE_THR && dd <= r2) {
                float dist = fsqrt_approx(dd);
                float eq   = (dist + MU_F) * frcp_approx(m + MU_F);
                float sv = swp ? dirJ : dirI;   // angle = atan2(sv, cv)
                float cv = swp ? dirI : dirJ;
                int bin;
                if (sv >= 0.0f) {
                    if (cv >= 0.0f) bin = (sv <= cv)  ? 0 : 1;
                    else            bin = (sv >= -cv) ? 2 : 3;
                } else {
                    if (cv <= 0.0f) bin = (-sv <= -cv) ? 4 : 5;
                    else            bin = (-sv >= cv)  ? 6 : 7;
                }
#pragma unroll
                for (int p = 0; p < PARTS; ++p)
                    lmin[p] = (bin == p) ? fminf(lmin[p], eq) : lmin[p];
            }
        }
    }

    // warp min-reduce per bin, then one smem atomic per warp per bin
#pragma unroll
    for (int p = 0; p < PARTS; ++p) {
        float v = lmin[p];
#pragma unroll
        for (int o = 16; o > 0; o >>= 1)
            v = fminf(v, __shfl_xor_sync(0xffffffffu, v, o));
        if (lane == 0)
            atomicMin(&smin[p], __float_as_int(v));  // values >= 0: int order == float order
    }
    __syncthreads();

    if (tid < MAXPARTS) {
        float fv = 0.0f, fd = 0.0f, fr = 0.0f;
        if (tid < PARTS) {
            float md = fminf(__int_as_float(smin[tid]), INF_F);
            if (md < INF_F) {
                fv = sp[6];   // ml
                fd = md;
                fr = (float)(6.283185307179586 * ((double)tid + 0.5) / 8.0);
            }
        }
        float* o = out + (size_t)b * (MAXPARTS * 3) + tid * 3;
        o[0] = fv; o[1] = fd; o[2] = fr;
    }
}

extern "C" void kernel_launch(void* const* d_in, const int* in_sizes, int n_in,
                              void* d_out, int out_size)
{
    const float* seg_maps      = (const float*)d_in[0];
    const float* seg_map_paras = (const float*)d_in[1];
    const float* trajectories  = (const float*)d_in[2];
    const float* current_pos   = (const float*)d_in[3];
    float* out = (float*)d_out;

    int B = in_sizes[0] / NPIX;   // 1024
    pc_kernel<<<B, BLOCK>>>(seg_maps, seg_map_paras, trajectories,
                            current_pos, out);
}

// round 11
// speedup vs baseline: 1.2832x; 1.0025x over previous
#include <cuda_runtime.h>
#include <math.h>

#define NS        100
#define NPIX      (NS * NS)
#define PARTS     8
#define MAXPARTS  16
#define BLOCK     256
#define U         8
#define NCTA      740      // 148 SMs * 5 CTAs/SM -> exactly one wave
#define INF_F     1000000000.0f
#define MU_F      1e-8f
#define SAFE_THR  0.05f

__device__ __forceinline__ float fsqrt_approx(float x) {
    float r; asm("sqrt.approx.f32 %0, %1;" : "=f"(r) : "f"(x)); return r;
}
__device__ __forceinline__ float frcp_approx(float x) {
    float r; asm("rcp.approx.f32 %0, %1;" : "=f"(r) : "f"(x)); return r;
}

__global__ __launch_bounds__(BLOCK, 5)
void pc_kernel(const float* __restrict__ seg_maps,      // (B,100,100)
               const float* __restrict__ seg_map_paras, // (B,6)
               const float* __restrict__ trajectories,  // (B,8,2)
               const float* __restrict__ current_pos,   // (B,1,2)
               float* __restrict__ out,                 // (B,16,3)
               int B)
{
    const int tid  = threadIdx.x;
    const int lane = tid & 31;

    __shared__ float sraw[12];
    __shared__ int   smin[PARTS];

    for (int b = blockIdx.x; b < B; b += gridDim.x) {

        // parallel preamble: one memory round, 12 scalars
        if (tid < 6)       sraw[tid] = __ldg(seg_map_paras + b * 6 + tid);
        else if (tid < 8)  sraw[tid] = __ldg(trajectories + b * 16 + (tid - 6));       // tr0x, tr0y
        else if (tid < 10) sraw[tid] = __ldg(trajectories + b * 16 + 14 + (tid - 8));  // tr7x, tr7y
        else if (tid < 12) sraw[tid] = __ldg(current_pos + b * 2 + (tid - 10));        // cx, cy
        if (tid < PARTS)   smin[tid] = __float_as_int(INF_F);
        __syncthreads();

        // redundant per-thread derivation (ALU only, no serial section)
        const float W0 = sraw[0], W1 = sraw[1], b0 = sraw[2], b1 = sraw[3];
        const bool  swp = (sraw[4] == 1.0f);
        const float mvx = sraw[8] - sraw[6];
        const float mvy = sraw[9] - sraw[7];
        const float ml  = sqrtf(mvx * mvx + mvy * mvy);
        const float r   = 2.0f * ml;
        const float cx  = sraw[10], cy = sraw[11];

        const float invW0 = 1.0f / W0;
        const float invW1 = 1.0f / W1;
        const float offI = -b0 * invW0 - (swp ? cy : cx);
        const float offJ = -b1 * invW1 - (swp ? cx : cy);

        // conservative pixel-space bbox of the valid disk (+/-1 px margin);
        // scanning extra pixels never changes the result (exact dd<=r2 test).
        int il = (int)floorf((-r - offI) * W0) - 1;
        int ih = (int)ceilf (( r - offI) * W0) + 1;
        int jl = (int)floorf((-r - offJ) * W1) - 1;
        int jh = (int)ceilf (( r - offJ) * W1) + 1;
        il = max(il, 0);  ih = min(ih, NS - 1);
        jl = max(jl, 0);  jh = min(jh, NS - 1);
        if (jh == jl) { if (jh < NS - 1) ++jh; else --jl; }   // Wd >= 2

        const int Wd = jh - jl + 1;
        const int Hd = ih - il + 1;
        const int tot = (Wd > 0 && Hd > 0) ? Wd * Hd : 0;

        // exact division by Wd for idx <= 10000: qi = umulhi(idx, M)
        const unsigned M = ((2097152u + (unsigned)Wd - 1u) / (unsigned)Wd) << 11;

        const float offIp = fmaf((float)il, invW0, offI);
        const float offJp = fmaf((float)jl, invW1, offJ);
        const float r2 = r * r;
        const float* base = seg_maps + (size_t)b * NPIX + (il * NS + jl);
        const int rowadj = NS - Wd;

        float lmin[PARTS];
#pragma unroll
        for (int p = 0; p < PARTS; ++p) lmin[p] = INF_F;

        for (int lo = 0; lo < tot; lo += BLOCK * U) {
            float mv[U];
#pragma unroll
            for (int k = 0; k < U; ++k) {
                int idx = lo + k * BLOCK + tid;
                int cidx = (idx < tot) ? idx : 0;           // clamped, in-bounds
                int qi  = (int)__umulhi((unsigned)cidx, M); // exact cidx / Wd
                mv[k]   = (idx < tot) ? __ldg(base + cidx + qi * rowadj) : 0.0f;
            }
#pragma unroll
            for (int k = 0; k < U; ++k) {
                int idx = lo + k * BLOCK + tid;
                int cidx = (idx < tot) ? idx : 0;
                int qi = (int)__umulhi((unsigned)cidx, M);
                int qj = cidx - qi * Wd;
                float m    = mv[k];
                float dirI = fmaf((float)qi, invW0, offIp);
                float dirJ = fmaf((float)qj, invW1, offJp);
                float dd   = fmaf(dirJ, dirJ, dirI * dirI);
                if (idx < tot && m > SAFE_THR && dd <= r2) {
                    float dist = fsqrt_approx(dd);
                    float eq   = (dist + MU_F) * frcp_approx(m + MU_F);
                    float sv = swp ? dirJ : dirI;   // angle = atan2(sv, cv)
                    float cv = swp ? dirI : dirJ;
                    int bin;
                    if (sv >= 0.0f) {
                        if (cv >= 0.0f) bin = (sv <= cv)  ? 0 : 1;
                        else            bin = (sv >= -cv) ? 2 : 3;
                    } else {
                        if (cv <= 0.0f) bin = (-sv <= -cv) ? 4 : 5;
                        else            bin = (-sv >= cv)  ? 6 : 7;
                    }
#pragma unroll
                    for (int p = 0; p < PARTS; ++p)
                        lmin[p] = (bin == p) ? fminf(lmin[p], eq) : lmin[p];
                }
            }
        }

        // warp min-reduce per bin, then one smem atomic per warp per bin
#pragma unroll
        for (int p = 0; p < PARTS; ++p) {
            float v = lmin[p];
#pragma unroll
            for (int o = 16; o > 0; o >>= 1)
                v = fminf(v, __shfl_xor_sync(0xffffffffu, v, o));
            if (lane == 0)
                atomicMin(&smin[p], __float_as_int(v));  // vals >= 0: int order == float order
        }
        __syncthreads();

        if (tid < MAXPARTS) {
            float fv = 0.0f, fd = 0.0f, fr = 0.0f;
            if (tid < PARTS) {
                float md = fminf(__int_as_float(smin[tid]), INF_F);
                if (md < INF_F) {
                    fv = ml;
                    fd = md;
                    fr = (float)(6.283185307179586 * ((double)tid + 0.5) / 8.0);
                }
            }
            float* o = out + (size_t)b * (MAXPARTS * 3) + tid * 3;
            o[0] = fv; o[1] = fd; o[2] = fr;
        }
        __syncthreads();   // protect sraw/smin reuse in next batch
    }
}

extern "C" void kernel_launch(void* const* d_in, const int* in_sizes, int n_in,
                              void* d_out, int out_size)
{
    const float* seg_maps      = (const float*)d_in[0];
    const float* seg_map_paras = (const float*)d_in[1];
    const float* trajectories  = (const float*)d_in[2];
    const float* current_pos   = (const float*)d_in[3];
    float* out = (float*)d_out;

    int B = in_sizes[0] / NPIX;   // 1024
    int grid = (B < NCTA) ? B : NCTA;
    pc_kernel<<<grid, BLOCK>>>(seg_maps, seg_map_paras, trajectories,
                               current_pos, out, B);
}